// round 1
// baseline (speedup 1.0000x reference)
#include <cuda_runtime.h>
#include <math.h>

#define BB 4
#define HH 8
#define TT 8192
#define DD 64
#define CC 64
#define WSZ 128
#define BH (BB*HH)
#define NOUT (BB*HH*TT*DD)          // 16,777,216 floats
#define LOSSP (BH*(TT/256))         // 1024 loss partials

// transposed smem pads
#define TP 136                      // [64][136] for qT, kT, rwT
#define VP 68                       // v row-major [128][68]
#define DP 129                      // dots [128][129]

// ---------------- scratch (device globals; no allocation) ----------------
__device__ float g_dists[(size_t)BH*CC*TT];   // 64 MB  (b,h,c,t)
__device__ int   g_idx[BH*CC*WSZ];            // 1 MB
__device__ float g_cnt[BH*TT];                // 1 MB
__device__ float g_losspart[LOSSP];

// ---------------- K0: zero out + cnt ----------------
__global__ void k_zero(float* __restrict__ out) {
    size_t i = (size_t)blockIdx.x * blockDim.x + threadIdx.x;
    if (i < (size_t)(NOUT/4)) ((float4*)out)[i] = make_float4(0.f,0.f,0.f,0.f);
    if (i < (size_t)(BH*TT)) g_cnt[i] = 0.f;
}

// ---------------- K1: dists + loss partials ----------------
__global__ void __launch_bounds__(256) k_dists(const float* __restrict__ qk,
                                               const float* __restrict__ means) {
    int bh = blockIdx.y, h = bh & (HH-1);
    int tid = threadIdx.x;
    __shared__ float ms[CC*DD];
    for (int i = tid; i < CC*DD; i += 256) ms[i] = means[h*CC*DD + i];
    __syncthreads();

    int tok = blockIdx.x*256 + tid;
    const float4* qr = (const float4*)(qk + ((size_t)bh*TT + tok)*DD);
    float q[DD];
    float ss = 0.f;
    #pragma unroll
    for (int f = 0; f < DD/4; f++) {
        float4 a = __ldg(qr + f);
        q[4*f+0]=a.x; q[4*f+1]=a.y; q[4*f+2]=a.z; q[4*f+3]=a.w;
        ss += a.x*a.x + a.y*a.y + a.z*a.z + a.w*a.w;
    }
    float inv = 1.f / fmaxf(sqrtf(ss), 1e-12f);

    float mx = -1e30f;
    float* drow = g_dists + (size_t)bh*CC*TT + tok;
    #pragma unroll 4
    for (int c = 0; c < CC; c++) {
        const float4* m4 = (const float4*)(ms + c*DD);
        float acc = 0.f;
        #pragma unroll
        for (int f = 0; f < DD/4; f++) {
            float4 m = m4[f];
            acc += q[4*f+0]*m.x + q[4*f+1]*m.y + q[4*f+2]*m.z + q[4*f+3]*m.w;
        }
        acc *= inv;
        drow[(size_t)c*TT] = acc;
        mx = fmaxf(mx, acc);
    }
    // |k|^2 + |m|^2 - 2 max dot   (means are unit-norm by construction)
    float term = ss*inv*inv + 1.0f - 2.0f*mx;

    __shared__ float red[256];
    red[tid] = term; __syncthreads();
    for (int s = 128; s > 0; s >>= 1) { if (tid < s) red[tid] += red[tid+s]; __syncthreads(); }
    if (tid == 0) g_losspart[blockIdx.y*(TT/256) + blockIdx.x] = red[0];
}

// ---------------- K2: top-128 per (b,h,c), sorted ascending ----------------
__device__ __forceinline__ unsigned fkey(float f) {
    unsigned u = __float_as_uint(f);
    return (u & 0x80000000u) ? ~u : (u | 0x80000000u);
}
__global__ void __launch_bounds__(256) k_topk() {
    int row = blockIdx.x;            // bh*CC + c
    int tid = threadIdx.x;
    __shared__ unsigned keys[TT];
    __shared__ int hist[256];
    __shared__ int s_bin, s_above, s_c, s_cnt;
    __shared__ int s_sel[WSZ];

    const float* dr = g_dists + (size_t)row*TT;
    for (int t = tid; t < TT; t += 256) keys[t] = fkey(dr[t]);
    __syncthreads();

    unsigned prefix = 0, pmask = 0;
    int need = WSZ;
    for (int pass = 0; pass < 4; pass++) {
        int sh = 24 - 8*pass;
        hist[tid] = 0;
        __syncthreads();
        for (int t = tid; t < TT; t += 256) {
            unsigned u = keys[t];
            if ((u & pmask) == prefix) atomicAdd(&hist[(u>>sh)&255], 1);
        }
        __syncthreads();
        if (tid == 0) {
            int acc = 0, b = 255;
            for (; b > 0; b--) { if (acc + hist[b] >= need) break; acc += hist[b]; }
            s_bin = b; s_above = acc;
        }
        __syncthreads();
        prefix |= ((unsigned)s_bin) << sh;
        pmask  |= 255u << sh;
        need  -= s_above;
        __syncthreads();
    }
    unsigned T = prefix;   // threshold key; `need` = # of ==T to take (smallest indices)

    // binary search: smallest X with |{t<X : keys[t]==T}| >= need
    int lo = 0, hi = TT;
    while (lo < hi) {
        int mid = (lo + hi) >> 1;   // count for X = mid
        if (tid == 0) s_c = 0;
        __syncthreads();
        int local = 0;
        for (int t = tid; t < mid; t += 256) local += (keys[t] == T);
        atomicAdd(&s_c, local);
        __syncthreads();
        int c = s_c;
        __syncthreads();
        if (c >= need) hi = mid; else lo = mid + 1;
    }
    int X = lo;

    if (tid == 0) s_cnt = 0;
    __syncthreads();
    for (int t = tid; t < TT; t += 256) {
        unsigned u = keys[t];
        if (u > T || (u == T && t < X)) {
            int p = atomicAdd(&s_cnt, 1);
            s_sel[p] = t;
        }
    }
    __syncthreads();

    // bitonic sort 128 indices ascending
    for (int k = 2; k <= WSZ; k <<= 1) {
        for (int j = k >> 1; j > 0; j >>= 1) {
            if (tid < WSZ) {
                int ixj = tid ^ j;
                if (ixj > tid) {
                    int a = s_sel[tid], b = s_sel[ixj];
                    bool up = ((tid & k) == 0);
                    if ((a > b) == up) { s_sel[tid] = b; s_sel[ixj] = a; }
                }
            }
            __syncthreads();
        }
    }
    if (tid < WSZ) g_idx[row*WSZ + tid] = s_sel[tid];
}

// ---------------- K3: per-cluster attention + scatter ----------------
__global__ void __launch_bounds__(256, 1) k_attn(const float* __restrict__ qk,
                                                 const float* __restrict__ v,
                                                 const float* __restrict__ rel_w,
                                                 float* __restrict__ out) {
    extern __shared__ float sm[];
    float* sqT  = sm;                 // [64][TP]  q transposed (d-major)
    float* skT  = sqT + DD*TP;        // [64][TP]  normalized k
    float* srwT = skT + DD*TP;        // [64][TP]  rel_w[:,h,:] transposed, cols 128..135 zero
    float* sv   = srwT + DD*TP;       // [128][VP] v row-major
    float* sd   = sv + WSZ*VP;        // [128][DP] dots / attn
    int*  sidx  = (int*)(sd + WSZ*DP);

    int blk = blockIdx.x;
    int bh  = blk / CC;
    int h   = bh & (HH-1);
    int tid = threadIdx.x;

    if (tid < WSZ) sidx[tid] = g_idx[blk*WSZ + tid];
    __syncthreads();

    const float* qbase = qk + (size_t)bh*TT*DD;
    const float* vbase = v  + (size_t)bh*TT*DD;

    // zero the rel pad columns (m in [128,136))
    for (int i = tid; i < DD*8; i += 256) srwT[(i>>3)*TP + WSZ + (i&7)] = 0.f;

    // gather q, v; load rel_w row h; transpose q/rel into [d][row]
    for (int i = tid; i < WSZ*16; i += 256) {
        int r = i & 127, f = i >> 7;          // f in [0,16): which float4 of the 64-d row
        int tkn = sidx[r];
        float4 a = __ldg((const float4*)(qbase + (size_t)tkn*DD) + f);
        sqT[(4*f+0)*TP + r] = a.x; sqT[(4*f+1)*TP + r] = a.y;
        sqT[(4*f+2)*TP + r] = a.z; sqT[(4*f+3)*TP + r] = a.w;
        float4 b = __ldg((const float4*)(vbase + (size_t)tkn*DD) + f);
        ((float4*)(sv + r*VP))[f] = b;
        float4 c = __ldg((const float4*)(rel_w + ((size_t)r*HH + h)*DD) + f);
        srwT[(4*f+0)*TP + r] = c.x; srwT[(4*f+1)*TP + r] = c.y;
        srwT[(4*f+2)*TP + r] = c.z; srwT[(4*f+3)*TP + r] = c.w;
    }
    __syncthreads();

    // normalized k
    if (tid < WSZ) {
        float ss = 0.f;
        #pragma unroll
        for (int d = 0; d < DD; d++) { float x = sqT[d*TP + tid]; ss += x*x; }
        float inv = 1.f / fmaxf(sqrtf(ss), 1e-12f);
        #pragma unroll
        for (int d = 0; d < DD; d++) skT[d*TP + tid] = sqT[d*TP + tid]*inv;
    }
    __syncthreads();

    // dots = (q . k^T + shifted rel) * 0.125 ; GEMM 128x128x64, 16x16 threads x 8x8 tile
    {
        int tx = tid & 15, ty = tid >> 4;
        int i0 = ty*8, j0 = tx*8;
        int m_lo = 120 - i0 + j0;             // 8-aligned; rel valid iff m <= 127 (pad cols are 0)
        bool has_rel = (j0 <= i0 + 7);
        float acc[8][8];
        #pragma unroll
        for (int r = 0; r < 8; r++)
            #pragma unroll
            for (int c = 0; c < 8; c++) acc[r][c] = 0.f;

        for (int kk = 0; kk < DD; kk++) {
            const float* qrow = sqT  + kk*TP;
            const float* krow = skT  + kk*TP;
            const float* wrow = srwT + kk*TP;
            float a[8], bq[8], rw[16];
            float4 a0 = ((const float4*)(qrow + i0))[0];
            float4 a1 = ((const float4*)(qrow + i0))[1];
            a[0]=a0.x; a[1]=a0.y; a[2]=a0.z; a[3]=a0.w;
            a[4]=a1.x; a[5]=a1.y; a[6]=a1.z; a[7]=a1.w;
            float4 b0 = ((const float4*)(krow + j0))[0];
            float4 b1 = ((const float4*)(krow + j0))[1];
            bq[0]=b0.x; bq[1]=b0.y; bq[2]=b0.z; bq[3]=b0.w;
            bq[4]=b1.x; bq[5]=b1.y; bq[6]=b1.z; bq[7]=b1.w;
            if (has_rel) {
                #pragma unroll
                for (int w4 = 0; w4 < 4; w4++) {
                    float4 wv = ((const float4*)(wrow + m_lo))[w4];
                    rw[4*w4+0]=wv.x; rw[4*w4+1]=wv.y; rw[4*w4+2]=wv.z; rw[4*w4+3]=wv.w;
                }
                #pragma unroll
                for (int r = 0; r < 8; r++)
                    #pragma unroll
                    for (int c = 0; c < 8; c++) {
                        acc[r][c] += a[r]*bq[c];
                        acc[r][c] += a[r]*rw[7 + c - r];
                    }
            } else {
                #pragma unroll
                for (int r = 0; r < 8; r++)
                    #pragma unroll
                    for (int c = 0; c < 8; c++) acc[r][c] += a[r]*bq[c];
            }
        }
        #pragma unroll
        for (int r = 0; r < 8; r++) {
            int i = i0 + r;
            #pragma unroll
            for (int c = 0; c < 8; c++) {
                int j = j0 + c;
                float val = acc[r][c]*0.125f;
                if (i == j) val = -50000.0f;
                sd[i*DP + j] = val;
            }
        }
    }
    __syncthreads();

    // row softmax
    if (tid < WSZ) {
        float* row = sd + tid*DP;
        float mx = -1e30f;
        #pragma unroll 8
        for (int j = 0; j < WSZ; j++) mx = fmaxf(mx, row[j]);
        float sum = 0.f;
        #pragma unroll 8
        for (int j = 0; j < WSZ; j++) { float e = __expf(row[j]-mx); row[j] = e; sum += e; }
        float rinv = 1.f/sum;
        #pragma unroll 8
        for (int j = 0; j < WSZ; j++) row[j] *= rinv;
    }
    __syncthreads();

    // bo = attn @ v, scatter-add into out; thread -> (row, half of d)
    {
        int irow = tid >> 1, half = (tid & 1)*32;
        float4 acc4[8];
        #pragma unroll
        for (int x = 0; x < 8; x++) acc4[x] = make_float4(0.f,0.f,0.f,0.f);
        for (int j = 0; j < WSZ; j++) {
            float a = sd[irow*DP + j];
            const float4* vv = (const float4*)(sv + j*VP + half);
            #pragma unroll
            for (int x = 0; x < 8; x++) {
                float4 t4 = vv[x];
                acc4[x].x += a*t4.x; acc4[x].y += a*t4.y;
                acc4[x].z += a*t4.z; acc4[x].w += a*t4.w;
            }
        }
        int tkn = sidx[irow];
        float* ob = out + ((size_t)bh*TT + tkn)*DD + half;
        #pragma unroll
        for (int x = 0; x < 8; x++) {
            atomicAdd(ob + 4*x + 0, acc4[x].x);
            atomicAdd(ob + 4*x + 1, acc4[x].y);
            atomicAdd(ob + 4*x + 2, acc4[x].z);
            atomicAdd(ob + 4*x + 3, acc4[x].w);
        }
        if (tid < WSZ) atomicAdd(&g_cnt[bh*TT + sidx[tid]], 1.0f);
    }
}

// ---------------- K4: divide by counts ----------------
__global__ void k_final(float* __restrict__ out) {
    size_t i = (size_t)blockIdx.x * blockDim.x + threadIdx.x;
    if (i < (size_t)(NOUT/4)) {
        float c = g_cnt[i >> 4];
        float inv = 1.f/(c + 1e-5f);
        float4 o = ((float4*)out)[i];
        o.x *= inv; o.y *= inv; o.z *= inv; o.w *= inv;
        ((float4*)out)[i] = o;
    }
}

// ---------------- K5: loss ----------------
__global__ void k_loss(float* __restrict__ out, int out_size) {
    __shared__ float red[256];
    int tid = threadIdx.x;
    float s = 0.f;
    for (int i = tid; i < LOSSP; i += 256) s += g_losspart[i];
    red[tid] = s; __syncthreads();
    for (int st = 128; st > 0; st >>= 1) { if (tid < st) red[tid] += red[tid+st]; __syncthreads(); }
    if (tid == 0 && out_size > NOUT) out[NOUT] = red[0] * (1e-4f / (float)NOUT);
}

extern "C" void kernel_launch(void* const* d_in, const int* in_sizes, int n_in,
                              void* d_out, int out_size) {
    const float* qk    = (const float*)d_in[0];
    const float* v     = (const float*)d_in[1];
    const float* means = (const float*)d_in[2];
    const float* rel_w = (const float*)d_in[3];
    float* out = (float*)d_out;

    const size_t SMEM_ATTN = (size_t)(3*DD*TP + WSZ*VP + WSZ*DP)*sizeof(float)
                             + WSZ*sizeof(int);   // ~206 KB
    cudaFuncSetAttribute(k_attn, cudaFuncAttributeMaxDynamicSharedMemorySize,
                         (int)SMEM_ATTN);

    k_zero <<<(NOUT/4 + 255)/256, 256>>>(out);
    k_dists<<<dim3(TT/256, BH), 256>>>(qk, means);
    k_topk <<<BH*CC, 256>>>();
    k_attn <<<BH*CC, 256, SMEM_ATTN>>>(qk, v, rel_w, out);
    k_final<<<(NOUT/4 + 255)/256, 256>>>(out);
    k_loss <<<1, 256>>>(out, out_size);
}

// round 3
// speedup vs baseline: 1.8942x; 1.8942x over previous
#include <cuda_runtime.h>
#include <math.h>
#include <stdint.h>

#define BB 4
#define HH 8
#define TT 8192
#define DD 64
#define CC 64
#define WSZ 128
#define BH (BB*HH)
#define NOUT (BB*HH*TT*DD)
#define LOSSP (BH*(TT/256))

// ---------------- scratch (device globals; no allocation) ----------------
__device__ float g_dists[(size_t)BH*CC*TT];   // 64 MB
__device__ int   g_idx[BH*CC*WSZ];
__device__ float g_cnt[BH*TT];
__device__ float g_losspart[LOSSP];

// ---------------- K0: zero out + cnt ----------------
__global__ void k_zero(float* __restrict__ out) {
    size_t i = (size_t)blockIdx.x * blockDim.x + threadIdx.x;
    if (i < (size_t)(NOUT/4)) ((float4*)out)[i] = make_float4(0.f,0.f,0.f,0.f);
    if (i < (size_t)(BH*TT)) g_cnt[i] = 0.f;
}

// ---------------- K1: dists + loss partials ----------------
__global__ void __launch_bounds__(256) k_dists(const float* __restrict__ qk,
                                               const float* __restrict__ means) {
    int bh = blockIdx.y, h = bh & (HH-1);
    int tid = threadIdx.x;
    __shared__ float ms[CC*DD];
    for (int i = tid; i < CC*DD; i += 256) ms[i] = means[h*CC*DD + i];
    __syncthreads();

    int tok = blockIdx.x*256 + tid;
    const float4* qr = (const float4*)(qk + ((size_t)bh*TT + tok)*DD);
    float q[DD];
    float ss = 0.f;
    #pragma unroll
    for (int f = 0; f < DD/4; f++) {
        float4 a = __ldg(qr + f);
        q[4*f+0]=a.x; q[4*f+1]=a.y; q[4*f+2]=a.z; q[4*f+3]=a.w;
        ss += a.x*a.x + a.y*a.y + a.z*a.z + a.w*a.w;
    }
    float inv = 1.f / fmaxf(sqrtf(ss), 1e-12f);

    float mx = -1e30f;
    float* drow = g_dists + (size_t)bh*CC*TT + tok;
    #pragma unroll 4
    for (int c = 0; c < CC; c++) {
        const float4* m4 = (const float4*)(ms + c*DD);
        float acc = 0.f;
        #pragma unroll
        for (int f = 0; f < DD/4; f++) {
            float4 m = m4[f];
            acc += q[4*f+0]*m.x + q[4*f+1]*m.y + q[4*f+2]*m.z + q[4*f+3]*m.w;
        }
        acc *= inv;
        drow[(size_t)c*TT] = acc;
        mx = fmaxf(mx, acc);
    }
    float term = ss*inv*inv + 1.0f - 2.0f*mx;

    __shared__ float red[256];
    red[tid] = term; __syncthreads();
    for (int s = 128; s > 0; s >>= 1) { if (tid < s) red[tid] += red[tid+s]; __syncthreads(); }
    if (tid == 0) g_losspart[blockIdx.y*(TT/256) + blockIdx.x] = red[0];
}

// ---------------- K2: top-128 per (b,h,c), sorted ascending ----------------
__device__ __forceinline__ unsigned fkey(float f) {
    unsigned u = __float_as_uint(f);
    return (u & 0x80000000u) ? ~u : (u | 0x80000000u);
}
__global__ void __launch_bounds__(256) k_topk() {
    int row = blockIdx.x;
    int tid = threadIdx.x;
    __shared__ unsigned keys[TT];
    __shared__ int hist[256];
    __shared__ int s_bin, s_above, s_c, s_cnt;
    __shared__ int s_sel[WSZ];

    const float* dr = g_dists + (size_t)row*TT;
    for (int t = tid; t < TT; t += 256) keys[t] = fkey(dr[t]);
    __syncthreads();

    unsigned prefix = 0, pmask = 0;
    int need = WSZ;
    for (int pass = 0; pass < 4; pass++) {
        int sh = 24 - 8*pass;
        hist[tid] = 0;
        __syncthreads();
        for (int t = tid; t < TT; t += 256) {
            unsigned u = keys[t];
            if ((u & pmask) == prefix) atomicAdd(&hist[(u>>sh)&255], 1);
        }
        __syncthreads();
        if (tid == 0) {
            int acc = 0, b = 255;
            for (; b > 0; b--) { if (acc + hist[b] >= need) break; acc += hist[b]; }
            s_bin = b; s_above = acc;
        }
        __syncthreads();
        prefix |= ((unsigned)s_bin) << sh;
        pmask  |= 255u << sh;
        need  -= s_above;
        __syncthreads();
    }
    unsigned T = prefix;

    int lo = 0, hi = TT;
    while (lo < hi) {
        int mid = (lo + hi) >> 1;
        if (tid == 0) s_c = 0;
        __syncthreads();
        int local = 0;
        for (int t = tid; t < mid; t += 256) local += (keys[t] == T);
        atomicAdd(&s_c, local);
        __syncthreads();
        int c = s_c;
        __syncthreads();
        if (c >= need) hi = mid; else lo = mid + 1;
    }
    int X = lo;

    if (tid == 0) s_cnt = 0;
    __syncthreads();
    for (int t = tid; t < TT; t += 256) {
        unsigned u = keys[t];
        if (u > T || (u == T && t < X)) {
            int p = atomicAdd(&s_cnt, 1);
            s_sel[p] = t;
        }
    }
    __syncthreads();

    for (int k = 2; k <= WSZ; k <<= 1) {
        for (int j = k >> 1; j > 0; j >>= 1) {
            if (tid < WSZ) {
                int ixj = tid ^ j;
                if (ixj > tid) {
                    int a = s_sel[tid], b = s_sel[ixj];
                    bool up = ((tid & k) == 0);
                    if ((a > b) == up) { s_sel[tid] = b; s_sel[ixj] = a; }
                }
            }
            __syncthreads();
        }
    }
    if (tid < WSZ) g_idx[row*WSZ + tid] = s_sel[tid];
}

// ================= mma.sync helpers (tf32, m16n8k8) =================
__device__ __forceinline__ uint32_t f2tf(float x){
    uint32_t u; asm("cvt.rna.tf32.f32 %0, %1;" : "=r"(u) : "f"(x)); return u;
}
__device__ __forceinline__ void mma8(float c[4], const uint32_t a[4], const uint32_t b[2]){
    asm volatile("mma.sync.aligned.m16n8k8.row.col.f32.tf32.tf32.f32 "
        "{%0,%1,%2,%3}, {%4,%5,%6,%7}, {%8,%9}, {%0,%1,%2,%3};"
        : "+f"(c[0]), "+f"(c[1]), "+f"(c[2]), "+f"(c[3])
        : "r"(a[0]), "r"(a[1]), "r"(a[2]), "r"(a[3]), "r"(b[0]), "r"(b[1]));
}
__device__ __forceinline__ void red2(float* p, float x, float y){
    asm volatile("red.global.add.v2.f32 [%0], {%1,%2};" :: "l"(p), "f"(x), "f"(y) : "memory");
}

// fragment-staging index helpers
// A (row-major m16k8): reg = row-half + 2*col-half; lane = (r&7)*4 + (k&3)
#define QIDX(r,k) (((((r)>>4)*8 + ((k)>>3))*32 + (((r)&7)*4 + ((k)&3)))*4 + (((r)>>3)&1) + 2*(((k)>>2)&1))
// B (col-major k8n8, N=128, ks=8): b0=B[tcol][g], b1=B[tcol+4][g]
#define KIDX(n,k) (((((n)>>3)*8 + ((k)>>3))*32 + (((n)&7)*4 + ((k)&3)))*2 + (((k)>>2)&1))
// B for AV (N=64, ks=16): element (j=kdim, d=ndim)
#define VIDX(j,d) (((((d)>>3)*16 + ((j)>>3))*32 + (((d)&7)*4 + ((j)&3)))*2 + (((j)>>2)&1))

#define SCP 136                 // scratch [j][i] stride (conflict-free frag reads)
// smem byte offsets
#define SM_Q  0                 // uint32 qf[8192]   32KB
#define SM_K  32768             // kf[8192]          32KB
#define SM_W  65536             // wf[8192]          32KB
#define SM_V  98304             // vf[8192]          32KB
#define SM_SC 131072            // float sc[128*136] 69632B
#define SM_IDX (SM_SC + WSZ*SCP*4)
#define SMEM_ATTN (SM_IDX + WSZ*4)   // 201,216 bytes

// ---------------- K3: per-cluster attention via mma.sync tf32 ----------------
__global__ void __launch_bounds__(256, 1) k_attn(const float* __restrict__ qk,
                                                 const float* __restrict__ v,
                                                 const float* __restrict__ rel_w,
                                                 float* __restrict__ out) {
    extern __shared__ char smem[];
    uint32_t* sQ = (uint32_t*)(smem + SM_Q);
    uint32_t* sK = (uint32_t*)(smem + SM_K);
    uint32_t* sW = (uint32_t*)(smem + SM_W);
    uint32_t* sV = (uint32_t*)(smem + SM_V);
    float*    sc = (float*)(smem + SM_SC);
    int*    sidx = (int*)(smem + SM_IDX);

    int tid = threadIdx.x;
    int wid = tid >> 5, lane = tid & 31;
    int g = lane >> 2, ct = lane & 3;
    int blk = blockIdx.x;
    int bh  = blk / CC;
    int h   = bh & (HH-1);

    if (tid < WSZ) sidx[tid] = g_idx[blk*WSZ + tid];
    // zero scratch (rel epilogue only fills j<=i)
    for (int x = tid; x < WSZ*SCP; x += 256) sc[x] = 0.f;
    __syncthreads();

    // ---- gather + fragment staging (tf32). thread -> (row r, k-half kh) ----
    {
        int r = tid >> 1, kh = tid & 1, k0 = kh*32;
        int tkn = sidx[r];
        const float4* q4 = (const float4*)(qk + ((size_t)bh*TT + tkn)*DD + k0);
        float4 qv[8];
        float ss = 0.f;
        #pragma unroll
        for (int f = 0; f < 8; f++) {
            qv[f] = __ldg(q4 + f);
            ss += qv[f].x*qv[f].x + qv[f].y*qv[f].y + qv[f].z*qv[f].z + qv[f].w*qv[f].w;
        }
        ss += __shfl_xor_sync(0xFFFFFFFFu, ss, 1);
        float inv = 1.f / fmaxf(sqrtf(ss), 1e-12f);
        #pragma unroll
        for (int f = 0; f < 8; f++) {
            float e[4] = {qv[f].x, qv[f].y, qv[f].z, qv[f].w};
            #pragma unroll
            for (int u = 0; u < 4; u++) {
                int k = k0 + 4*f + u;
                sQ[QIDX(r,k)] = f2tf(e[u]);
                sK[KIDX(r,k)] = f2tf(e[u]*inv);
            }
        }
        const float4* w4 = (const float4*)(rel_w + ((size_t)r*HH + h)*DD + k0);
        #pragma unroll
        for (int f = 0; f < 8; f++) {
            float4 wv = __ldg(w4 + f);
            float e[4] = {wv.x, wv.y, wv.z, wv.w};
            #pragma unroll
            for (int u = 0; u < 4; u++) sW[KIDX(r, k0 + 4*f + u)] = f2tf(e[u]);
        }
        const float4* v4 = (const float4*)(v + ((size_t)bh*TT + tkn)*DD + k0);
        #pragma unroll
        for (int f = 0; f < 8; f++) {
            float4 vv = __ldg(v4 + f);
            float e[4] = {vv.x, vv.y, vv.z, vv.w};
            #pragma unroll
            for (int u = 0; u < 4; u++) sV[VIDX(r, k0 + 4*f + u)] = f2tf(e[u]);
        }
    }
    __syncthreads();

    // warp tiling for 128x128 GEMMs: 2(m) x 4(n) warps, each 64x32
    int wm = wid >> 2, wn = wid & 3;

    // ---- GEMM A: R = q . rel_w^T ; epilogue scatters shift into sc[j][i] ----
    {
        float acc[4][4][4];
        #pragma unroll
        for (int a = 0; a < 4; a++)
            #pragma unroll
            for (int b = 0; b < 4; b++)
                #pragma unroll
                for (int e = 0; e < 4; e++) acc[a][b][e] = 0.f;
        #pragma unroll
        for (int ks = 0; ks < 8; ks++) {
            uint32_t af[4][4]; uint32_t bf[4][2];
            #pragma unroll
            for (int mt = 0; mt < 4; mt++)
                *(uint4*)af[mt] = *(const uint4*)&sQ[(((wm*4+mt)*8+ks)*32 + lane)*4];
            #pragma unroll
            for (int nt = 0; nt < 4; nt++)
                *(uint2*)bf[nt] = *(const uint2*)&sW[(((wn*4+nt)*8+ks)*32 + lane)*2];
            #pragma unroll
            for (int mt = 0; mt < 4; mt++)
                #pragma unroll
                for (int nt = 0; nt < 4; nt++) mma8(acc[mt][nt], af[mt], bf[nt]);
        }
        #pragma unroll
        for (int mt = 0; mt < 4; mt++) {
            int ia = wm*64 + mt*16 + g, ib = ia + 8;
            #pragma unroll
            for (int nt = 0; nt < 4; nt++) {
                int m0 = wn*32 + nt*8 + 2*ct;
                int j;
                j = m0   + ia - 127; if (j >= 0) sc[j*SCP + ia] = acc[mt][nt][0];
                j = m0+1 + ia - 127; if (j >= 0) sc[j*SCP + ia] = acc[mt][nt][1];
                j = m0   + ib - 127; if (j >= 0) sc[j*SCP + ib] = acc[mt][nt][2];
                j = m0+1 + ib - 127; if (j >= 0) sc[j*SCP + ib] = acc[mt][nt][3];
            }
        }
    }
    __syncthreads();

    // ---- GEMM B: QK = q . khat^T ; epilogue: +rel, scale, diag mask ----
    {
        float acc[4][4][4];
        #pragma unroll
        for (int a = 0; a < 4; a++)
            #pragma unroll
            for (int b = 0; b < 4; b++)
                #pragma unroll
                for (int e = 0; e < 4; e++) acc[a][b][e] = 0.f;
        #pragma unroll
        for (int ks = 0; ks < 8; ks++) {
            uint32_t af[4][4]; uint32_t bf[4][2];
            #pragma unroll
            for (int mt = 0; mt < 4; mt++)
                *(uint4*)af[mt] = *(const uint4*)&sQ[(((wm*4+mt)*8+ks)*32 + lane)*4];
            #pragma unroll
            for (int nt = 0; nt < 4; nt++)
                *(uint2*)bf[nt] = *(const uint2*)&sK[(((wn*4+nt)*8+ks)*32 + lane)*2];
            #pragma unroll
            for (int mt = 0; mt < 4; mt++)
                #pragma unroll
                for (int nt = 0; nt < 4; nt++) mma8(acc[mt][nt], af[mt], bf[nt]);
        }
        __syncthreads();   // rel writes done before combining (same barrier protects reads)
        #pragma unroll
        for (int mt = 0; mt < 4; mt++) {
            int ia = wm*64 + mt*16 + g, ib = ia + 8;
            #pragma unroll
            for (int nt = 0; nt < 4; nt++) {
                int j0 = wn*32 + nt*8 + 2*ct;
                float v0 = (acc[mt][nt][0] + sc[j0*SCP + ia])*0.125f;
                float v1 = (acc[mt][nt][1] + sc[(j0+1)*SCP + ia])*0.125f;
                float v2 = (acc[mt][nt][2] + sc[j0*SCP + ib])*0.125f;
                float v3 = (acc[mt][nt][3] + sc[(j0+1)*SCP + ib])*0.125f;
                if (j0   == ia) v0 = -50000.0f;
                if (j0+1 == ia) v1 = -50000.0f;
                if (j0   == ib) v2 = -50000.0f;
                if (j0+1 == ib) v3 = -50000.0f;
                sc[j0*SCP + ia] = v0; sc[(j0+1)*SCP + ia] = v1;
                sc[j0*SCP + ib] = v2; sc[(j0+1)*SCP + ib] = v3;
            }
        }
    }
    __syncthreads();

    // ---- softmax: 2 threads per row ----
    {
        int i = tid >> 1, jh = tid & 1, j0 = jh*64;
        float mx = -1e30f;
        #pragma unroll 8
        for (int jj = 0; jj < 64; jj++) mx = fmaxf(mx, sc[(j0+jj)*SCP + i]);
        mx = fmaxf(mx, __shfl_xor_sync(0xFFFFFFFFu, mx, 1));
        float sum = 0.f;
        #pragma unroll 8
        for (int jj = 0; jj < 64; jj++) {
            float e = __expf(sc[(j0+jj)*SCP + i] - mx);
            sc[(j0+jj)*SCP + i] = e;
            sum += e;
        }
        sum += __shfl_xor_sync(0xFFFFFFFFu, sum, 1);
        float rinv = 1.f/sum;
        uint32_t* scU = (uint32_t*)sc;
        #pragma unroll 8
        for (int jj = 0; jj < 64; jj++)
            scU[(j0+jj)*SCP + i] = f2tf(sc[(j0+jj)*SCP + i]*rinv);
    }
    __syncthreads();

    // ---- GEMM C: bo = attn @ v ; epilogue: red.v2 scatter ----
    {
        int wm2 = wid >> 1, wn2 = wid & 1;
        const uint32_t* scU = (const uint32_t*)sc;
        float acc[2][4][4];
        #pragma unroll
        for (int a = 0; a < 2; a++)
            #pragma unroll
            for (int b = 0; b < 4; b++)
                #pragma unroll
                for (int e = 0; e < 4; e++) acc[a][b][e] = 0.f;
        #pragma unroll
        for (int ks = 0; ks < 16; ks++) {
            uint32_t af[2][4]; uint32_t bf[4][2];
            int jr0 = 8*ks + ct;
            #pragma unroll
            for (int mt = 0; mt < 2; mt++) {
                int i0 = wm2*32 + mt*16;
                af[mt][0] = scU[jr0*SCP + i0 + g];
                af[mt][1] = scU[jr0*SCP + i0 + g + 8];
                af[mt][2] = scU[(jr0+4)*SCP + i0 + g];
                af[mt][3] = scU[(jr0+4)*SCP + i0 + g + 8];
            }
            #pragma unroll
            for (int nt = 0; nt < 4; nt++)
                *(uint2*)bf[nt] = *(const uint2*)&sV[(((wn2*4+nt)*16+ks)*32 + lane)*2];
            #pragma unroll
            for (int mt = 0; mt < 2; mt++)
                #pragma unroll
                for (int nt = 0; nt < 4; nt++) mma8(acc[mt][nt], af[mt], bf[nt]);
        }
        float* obase = out + (size_t)bh*TT*DD;
        #pragma unroll
        for (int mt = 0; mt < 2; mt++) {
            int ia = wm2*32 + mt*16 + g, ib = ia + 8;
            int ta = sidx[ia], tb = sidx[ib];
            #pragma unroll
            for (int nt = 0; nt < 4; nt++) {
                int d0 = wn2*32 + nt*8 + 2*ct;
                red2(obase + (size_t)ta*DD + d0, acc[mt][nt][0], acc[mt][nt][1]);
                red2(obase + (size_t)tb*DD + d0, acc[mt][nt][2], acc[mt][nt][3]);
            }
        }
        if (tid < WSZ) atomicAdd(&g_cnt[bh*TT + sidx[tid]], 1.0f);
    }
}

// ---------------- K4: divide by counts ----------------
__global__ void k_final(float* __restrict__ out) {
    size_t i = (size_t)blockIdx.x * blockDim.x + threadIdx.x;
    if (i < (size_t)(NOUT/4)) {
        float c = g_cnt[i >> 4];
        float inv = 1.f/(c + 1e-5f);
        float4 o = ((float4*)out)[i];
        o.x *= inv; o.y *= inv; o.z *= inv; o.w *= inv;
        ((float4*)out)[i] = o;
    }
}

// ---------------- K5: loss ----------------
__global__ void k_loss(float* __restrict__ out, int out_size) {
    __shared__ float red[256];
    int tid = threadIdx.x;
    float s = 0.f;
    for (int i = tid; i < LOSSP; i += 256) s += g_losspart[i];
    red[tid] = s; __syncthreads();
    for (int st = 128; st > 0; st >>= 1) { if (tid < st) red[tid] += red[tid+st]; __syncthreads(); }
    if (tid == 0 && out_size > NOUT) out[NOUT] = red[0] * (1e-4f / (float)NOUT);
}

extern "C" void kernel_launch(void* const* d_in, const int* in_sizes, int n_in,
                              void* d_out, int out_size) {
    const float* qk    = (const float*)d_in[0];
    const float* v     = (const float*)d_in[1];
    const float* means = (const float*)d_in[2];
    const float* rel_w = (const float*)d_in[3];
    float* out = (float*)d_out;

    cudaFuncSetAttribute(k_attn, cudaFuncAttributeMaxDynamicSharedMemorySize, SMEM_ATTN);

    k_zero <<<(NOUT/4 + 255)/256, 256>>>(out);
    k_dists<<<dim3(TT/256, BH), 256>>>(qk, means);
    k_topk <<<BH*CC, 256>>>();
    k_attn <<<BH*CC, 256, SMEM_ATTN>>>(qk, v, rel_w, out);
    k_final<<<(NOUT/4 + 255)/256, 256>>>(out);
    k_loss <<<1, 256>>>(out, out_size);
}